// round 2
// baseline (speedup 1.0000x reference)
#include <cuda_runtime.h>
#include <cstdint>

#define MAXN   1024
#define WIDTH  256
#define HEIGHT 256
#define EPS2D  0.3f
#define LOG2E  1.4426950408889634f

// scratch (sorted + temp), device globals per allocation rules
__device__ float4 dtA[MAXN], dtB[MAXN], dtBox[MAXN];
__device__ float4 dgA[MAXN], dgB[MAXN], dgBox[MAXN];

__device__ __forceinline__ float fast_ex2(float x) {
    float y; asm("ex2.approx.f32 %0, %1;" : "=f"(y) : "f"(x)); return y;
}
__device__ __forceinline__ float sigmoidf(float x) { return 1.f / (1.f + expf(-x)); }

// ---------------------------------------------------------------------------
// Kernel 1: per-gaussian preprocess + stable depth sort (bitonic on (z,idx))
// ---------------------------------------------------------------------------
__global__ __launch_bounds__(1024)
void prep_kernel(const float* __restrict__ means,
                 const float* __restrict__ quats,
                 const float* __restrict__ scales,
                 const float* __restrict__ opac,
                 const float* __restrict__ rgbs,
                 const float* __restrict__ vm,
                 const float* __restrict__ Km,
                 int n)
{
    __shared__ unsigned long long skey[MAXN];
    int i = threadIdx.x;
    unsigned long long key = 0xFFFFFFFFFFFFFFFFULL;

    if (i < n) {
        float R00=vm[0],R01=vm[1],R02=vm[2],t0=vm[3];
        float R10=vm[4],R11=vm[5],R12=vm[6],t1=vm[7];
        float R20=vm[8],R21=vm[9],R22=vm[10],t2=vm[11];
        float mx=means[3*i], my=means[3*i+1], mz=means[3*i+2];
        float px = R00*mx + R01*my + R02*mz + t0;
        float py = R10*mx + R11*my + R12*mz + t1;
        float pz = R20*mx + R21*my + R22*mz + t2;
        float fx=Km[0], cx=Km[2], fy=Km[4], cy=Km[5];
        float iz = 1.f / pz;
        float u = fx*px*iz + cx;
        float v = fy*py*iz + cy;

        // normalized quaternion -> rotation
        float qw=quats[4*i], qx=quats[4*i+1], qy=quats[4*i+2], qz=quats[4*i+3];
        float qin = 1.f / (sqrtf(qw*qw + qx*qx + qy*qy + qz*qz) + 1e-8f);
        qw*=qin; qx*=qin; qy*=qin; qz*=qin;
        float Rq[3][3];
        Rq[0][0]=1.f-2.f*(qy*qy+qz*qz); Rq[0][1]=2.f*(qx*qy-qw*qz); Rq[0][2]=2.f*(qx*qz+qw*qy);
        Rq[1][0]=2.f*(qx*qy+qw*qz); Rq[1][1]=1.f-2.f*(qx*qx+qz*qz); Rq[1][2]=2.f*(qy*qz-qw*qx);
        Rq[2][0]=2.f*(qx*qz-qw*qy); Rq[2][1]=2.f*(qy*qz+qw*qx); Rq[2][2]=1.f-2.f*(qx*qx+qy*qy);

        float s0=scales[3*i], s1=scales[3*i+1], s2=scales[3*i+2];
        float ss0=s0*s0, ss1=s1*s1, ss2=s2*s2;

        // S3 = Rq diag(s^2) Rq^T
        float S3[3][3];
        #pragma unroll
        for (int r=0;r<3;r++)
            #pragma unroll
            for (int c=0;c<3;c++)
                S3[r][c] = Rq[r][0]*Rq[c][0]*ss0 + Rq[r][1]*Rq[c][1]*ss1 + Rq[r][2]*Rq[c][2]*ss2;

        float Rv[3][3] = {{R00,R01,R02},{R10,R11,R12},{R20,R21,R22}};
        float tm[3][3], Sc[3][3];
        #pragma unroll
        for (int r=0;r<3;r++)
            #pragma unroll
            for (int c=0;c<3;c++)
                tm[r][c] = Rv[r][0]*S3[0][c] + Rv[r][1]*S3[1][c] + Rv[r][2]*S3[2][c];
        #pragma unroll
        for (int r=0;r<3;r++)
            #pragma unroll
            for (int c=0;c<3;c++)
                Sc[r][c] = tm[r][0]*Rv[c][0] + tm[r][1]*Rv[c][1] + tm[r][2]*Rv[c][2];

        // J (2x3) rows
        float j00 = fx*iz,          j02 = -fx*px*iz*iz;
        float j11 = fy*iz,          j12 = -fy*py*iz*iz;
        // w0 = Sc * j0,  w1 = Sc * j1
        float w0x = Sc[0][0]*j00 + Sc[0][2]*j02;
        float w0z = Sc[2][0]*j00 + Sc[2][2]*j02;
        float w1x = Sc[0][1]*j11 + Sc[0][2]*j12;
        float w1y = Sc[1][1]*j11 + Sc[1][2]*j12;
        float w1z = Sc[2][1]*j11 + Sc[2][2]*j12;

        float a = j00*w0x + j02*w0z + EPS2D;
        float b = j00*w1x + j02*w1z;
        float c = j11*w1y + j12*w1z + EPS2D;

        float det = a*c - b*b;
        float idet = 1.f / det;
        float ia =  c*idet;
        float ib = -b*idet;
        float ic =  a*idet;

        float op  = sigmoidf(opac[i]);
        float col = sigmoidf(rgbs[i]);

        float tau = logf(255.f * op);
        float4 box;
        if (tau > 0.f) {
            float rx = sqrtf(2.f*tau*a) + 1e-3f;
            float ry = sqrtf(2.f*tau*c) + 1e-3f;
            box = make_float4(u - rx, u + rx, v - ry, v + ry);
        } else {
            box = make_float4(1e9f, -1e9f, 1e9f, -1e9f);
        }

        dtA[i]   = make_float4(u, v, 0.5f*LOG2E*ia, LOG2E*ib);
        dtB[i]   = make_float4(0.5f*LOG2E*ic, op, col, 0.f);
        dtBox[i] = box;

        unsigned ub = __float_as_uint(pz);
        ub = (ub & 0x80000000u) ? ~ub : (ub | 0x80000000u);
        key = ((unsigned long long)ub << 32) | (unsigned)i;
    }
    skey[i] = key;
    __syncthreads();

    // bitonic sort (stable via idx tiebreak) — all 1024 keys
    for (unsigned k = 2; k <= MAXN; k <<= 1) {
        for (unsigned j = k >> 1; j > 0; j >>= 1) {
            unsigned ixj = (unsigned)i ^ j;
            if (ixj > (unsigned)i) {
                unsigned long long A = skey[i], B = skey[ixj];
                bool up = ((i & k) == 0);
                if ((A > B) == up) { skey[i] = B; skey[ixj] = A; }
            }
            __syncthreads();
        }
    }

    unsigned long long kk = skey[i];
    if (i < n) {
        int src = (int)(kk & 0xFFFFFFFFu);
        dgA[i]   = dtA[src];
        dgB[i]   = dtB[src];
        dgBox[i] = dtBox[src];
    }
}

// ---------------------------------------------------------------------------
// Kernel 2: tiled render, 16x16 px per block, fused bbox culling + compaction
// ---------------------------------------------------------------------------
__global__ __launch_bounds__(256)
void render_kernel(float* __restrict__ out, int n)
{
    __shared__ float4 sA[256];
    __shared__ float4 sB[256];
    __shared__ int sW[8];

    int tid  = threadIdx.x;
    int tx   = blockIdx.x & 15;
    int ty   = blockIdx.x >> 4;
    int x    = tx*16 + (tid & 15);
    int y    = ty*16 + (tid >> 4);
    float pxc = x + 0.5f, pyc = y + 0.5f;
    float tx0 = tx*16 + 0.5f,  tx1 = tx*16 + 15.5f;
    float ty0 = ty*16 + 0.5f,  ty1 = ty*16 + 15.5f;
    int lane = tid & 31, warp = tid >> 5;

    float T = 1.f, img = 0.f;

    for (int base = 0; base < n; base += 256) {
        int gi = base + tid;
        bool hit = false;
        if (gi < n) {
            float4 bb = dgBox[gi];
            hit = (bb.x <= tx1) & (bb.y >= tx0) & (bb.z <= ty1) & (bb.w >= ty0);
        }
        unsigned m = __ballot_sync(0xFFFFFFFFu, hit);
        if (lane == 0) sW[warp] = __popc(m);
        __syncthreads();

        int off = 0;
        #pragma unroll
        for (int w = 0; w < 8; w++) if (w < warp) off += sW[w];
        int total = sW[0]+sW[1]+sW[2]+sW[3]+sW[4]+sW[5]+sW[6]+sW[7];

        if (hit) {
            int pos = off + __popc(m & ((1u << lane) - 1u));
            sA[pos] = dgA[gi];
            sB[pos] = dgB[gi];
        }
        __syncthreads();

        if (T > 1e-4f) {
            for (int j = 0; j < total; j++) {
                float4 A = sA[j];
                float4 B = sB[j];
                float dx = pxc - A.x;
                float dy = pyc - A.y;
                // e = (log2e)*( 0.5*ia*dx^2 + 0.5*ic*dy^2 + ib*dx*dy ); alpha = op*2^-e
                float e = fmaf(A.z*dx, dx, fmaf(B.x*dy, dy, A.w*dx*dy));
                float alpha = B.y * fast_ex2(-e);
                alpha = fminf(alpha, 0.999f);
                if (e >= 0.f && alpha >= (1.0f/255.0f)) {
                    img = fmaf(alpha*T, B.z, img);
                    T *= (1.f - alpha);
                }
            }
        }
        if (__syncthreads_and(T <= 1e-4f)) break;
    }

    out[y*WIDTH + x] = img;
}

// ---------------------------------------------------------------------------
extern "C" void kernel_launch(void* const* d_in, const int* in_sizes, int n_in,
                              void* d_out, int out_size)
{
    const float* means   = (const float*)d_in[0];
    const float* quats   = (const float*)d_in[1];
    const float* scales  = (const float*)d_in[2];
    const float* opac    = (const float*)d_in[3];
    const float* rgbs    = (const float*)d_in[4];
    const float* viewmat = (const float*)d_in[5];
    const float* Km      = (const float*)d_in[6];
    int n = in_sizes[3];            // opacities: one per gaussian
    if (n > MAXN) n = MAXN;

    prep_kernel<<<1, 1024>>>(means, quats, scales, opac, rgbs, viewmat, Km, n);
    render_kernel<<<256, 256>>>((float*)d_out, n);
}

// round 3
// speedup vs baseline: 1.8989x; 1.8989x over previous
#include <cuda_runtime.h>
#include <cstdint>

#define MAXN   1024
#define WIDTH  256
#define HEIGHT 256
#define EPS2D  0.3f
#define LOG2E  1.4426950408889634f

// scratch (sorted + temp), device globals per allocation rules
__device__ float4 dtA[MAXN], dtB[MAXN], dtBox[MAXN];
__device__ float4 dgA[MAXN], dgB[MAXN], dgBox[MAXN];

__device__ __forceinline__ float fast_ex2(float x) {
    float y; asm("ex2.approx.f32 %0, %1;" : "=f"(y) : "f"(x)); return y;
}
__device__ __forceinline__ float sigmoidf(float x) { return 1.f / (1.f + expf(-x)); }

// ---------------------------------------------------------------------------
// Kernel 1: per-gaussian preprocess + depth sort.
// Fast path: if all view-space z identical (true for this dataset), a stable
// sort is the identity permutation -> skip the bitonic entirely.
// ---------------------------------------------------------------------------
__global__ __launch_bounds__(1024)
void prep_kernel(const float* __restrict__ means,
                 const float* __restrict__ quats,
                 const float* __restrict__ scales,
                 const float* __restrict__ opac,
                 const float* __restrict__ rgbs,
                 const float* __restrict__ vm,
                 const float* __restrict__ Km,
                 int n)
{
    __shared__ float s_pz0;
    __shared__ unsigned long long skey[MAXN];
    int i = threadIdx.x;

    float4 Aval, Bval, Boxval;
    float pz = 0.f;

    if (i < n) {
        float R00=vm[0],R01=vm[1],R02=vm[2],t0=vm[3];
        float R10=vm[4],R11=vm[5],R12=vm[6],t1=vm[7];
        float R20=vm[8],R21=vm[9],R22=vm[10],t2=vm[11];
        float mx=means[3*i], my=means[3*i+1], mz=means[3*i+2];
        float px = R00*mx + R01*my + R02*mz + t0;
        float py = R10*mx + R11*my + R12*mz + t1;
        pz       = R20*mx + R21*my + R22*mz + t2;
        float fx=Km[0], cx=Km[2], fy=Km[4], cy=Km[5];
        float iz = 1.f / pz;
        float u = fx*px*iz + cx;
        float v = fy*py*iz + cy;

        float qw=quats[4*i], qx=quats[4*i+1], qy=quats[4*i+2], qz=quats[4*i+3];
        float qin = 1.f / (sqrtf(qw*qw + qx*qx + qy*qy + qz*qz) + 1e-8f);
        qw*=qin; qx*=qin; qy*=qin; qz*=qin;
        float Rq[3][3];
        Rq[0][0]=1.f-2.f*(qy*qy+qz*qz); Rq[0][1]=2.f*(qx*qy-qw*qz); Rq[0][2]=2.f*(qx*qz+qw*qy);
        Rq[1][0]=2.f*(qx*qy+qw*qz); Rq[1][1]=1.f-2.f*(qx*qx+qz*qz); Rq[1][2]=2.f*(qy*qz-qw*qx);
        Rq[2][0]=2.f*(qx*qz-qw*qy); Rq[2][1]=2.f*(qy*qz+qw*qx); Rq[2][2]=1.f-2.f*(qx*qx+qy*qy);

        float s0=scales[3*i], s1=scales[3*i+1], s2=scales[3*i+2];
        float ss0=s0*s0, ss1=s1*s1, ss2=s2*s2;

        float S3[3][3];
        #pragma unroll
        for (int r=0;r<3;r++)
            #pragma unroll
            for (int c=0;c<3;c++)
                S3[r][c] = Rq[r][0]*Rq[c][0]*ss0 + Rq[r][1]*Rq[c][1]*ss1 + Rq[r][2]*Rq[c][2]*ss2;

        float Rv[3][3] = {{R00,R01,R02},{R10,R11,R12},{R20,R21,R22}};
        float tm[3][3], Sc[3][3];
        #pragma unroll
        for (int r=0;r<3;r++)
            #pragma unroll
            for (int c=0;c<3;c++)
                tm[r][c] = Rv[r][0]*S3[0][c] + Rv[r][1]*S3[1][c] + Rv[r][2]*S3[2][c];
        #pragma unroll
        for (int r=0;r<3;r++)
            #pragma unroll
            for (int c=0;c<3;c++)
                Sc[r][c] = tm[r][0]*Rv[c][0] + tm[r][1]*Rv[c][1] + tm[r][2]*Rv[c][2];

        float j00 = fx*iz,          j02 = -fx*px*iz*iz;
        float j11 = fy*iz,          j12 = -fy*py*iz*iz;
        float w0x = Sc[0][0]*j00 + Sc[0][2]*j02;
        float w0z = Sc[2][0]*j00 + Sc[2][2]*j02;
        float w1x = Sc[0][1]*j11 + Sc[0][2]*j12;
        float w1y = Sc[1][1]*j11 + Sc[1][2]*j12;
        float w1z = Sc[2][1]*j11 + Sc[2][2]*j12;

        float a = j00*w0x + j02*w0z + EPS2D;
        float b = j00*w1x + j02*w1z;
        float c = j11*w1y + j12*w1z + EPS2D;

        float det = a*c - b*b;
        float idet = 1.f / det;
        float ia =  c*idet;
        float ib = -b*idet;
        float ic =  a*idet;

        float op  = sigmoidf(opac[i]);
        float col = sigmoidf(rgbs[i]);

        float tau = logf(255.f * op);
        if (tau > 0.f) {
            float rx = sqrtf(2.f*tau*a) + 1e-3f;
            float ry = sqrtf(2.f*tau*c) + 1e-3f;
            Boxval = make_float4(u - rx, u + rx, v - ry, v + ry);
        } else {
            Boxval = make_float4(1e9f, -1e9f, 1e9f, -1e9f);
        }

        Aval = make_float4(u, v, 0.5f*LOG2E*ia, LOG2E*ib);
        Bval = make_float4(0.5f*LOG2E*ic, op, col, 0.f);
    }

    if (i == 0) s_pz0 = pz;
    __syncthreads();
    bool same = (i >= n) || (pz == s_pz0);
    if (__syncthreads_and(same)) {
        // stable sort of identical keys == identity
        if (i < n) { dgA[i] = Aval; dgB[i] = Bval; dgBox[i] = Boxval; }
        return;
    }

    // General path: bitonic sort on (z, idx)
    unsigned long long key = 0xFFFFFFFFFFFFFFFFULL;
    if (i < n) {
        dtA[i] = Aval; dtB[i] = Bval; dtBox[i] = Boxval;
        unsigned ub = __float_as_uint(pz);
        ub = (ub & 0x80000000u) ? ~ub : (ub | 0x80000000u);
        key = ((unsigned long long)ub << 32) | (unsigned)i;
    }
    skey[i] = key;
    __syncthreads();

    for (unsigned k = 2; k <= MAXN; k <<= 1) {
        for (unsigned j = k >> 1; j > 0; j >>= 1) {
            unsigned ixj = (unsigned)i ^ j;
            if (ixj > (unsigned)i) {
                unsigned long long A = skey[i], B = skey[ixj];
                bool up = ((i & k) == 0);
                if ((A > B) == up) { skey[i] = B; skey[ixj] = A; }
            }
            __syncthreads();
        }
    }

    unsigned long long kk = skey[i];
    if (i < n) {
        int src = (int)(kk & 0xFFFFFFFFu);
        dgA[i]   = dtA[src];
        dgB[i]   = dtB[src];
        dgBox[i] = dtBox[src];
    }
}

// ---------------------------------------------------------------------------
// Kernel 2: 8x8-px tiles, 1024 blocks, 256 threads = 64 pixels x 4 segments.
// Whole tile list compacted into shared once; each segment composites its
// contiguous (depth-ordered) quarter; segments combined via associativity of
// the "over" operator: (c1,T1) + (c2,T2) = (c1 + T1*c2, T1*T2).
// ---------------------------------------------------------------------------
#define NSEG 4

__global__ __launch_bounds__(256)
void render_kernel(float* __restrict__ out, int n)
{
    __shared__ float4 sA[MAXN];
    __shared__ float4 sB[MAXN];
    __shared__ int    sW[8];
    __shared__ float  segC[NSEG][64];
    __shared__ float  segT[NSEG][64];

    int tid  = threadIdx.x;
    int lane = tid & 31, warp = tid >> 5;
    int seg  = tid >> 6;          // 0..3
    int pix  = tid & 63;          // 0..63
    int tx   = blockIdx.x & 31;
    int ty   = blockIdx.x >> 5;
    int x    = tx*8 + (pix & 7);
    int y    = ty*8 + (pix >> 3);
    float pxc = x + 0.5f, pyc = y + 0.5f;
    float tx0 = tx*8 + 0.5f,  tx1 = tx*8 + 7.5f;
    float ty0 = ty*8 + 0.5f,  ty1 = ty*8 + 7.5f;

    // ---- cull + order-preserving compaction of whole tile list ----
    int total = 0;
    for (int base = 0; base < n; base += 256) {
        int gi = base + tid;
        bool hit = false;
        if (gi < n) {
            float4 bb = dgBox[gi];
            hit = (bb.x <= tx1) & (bb.y >= tx0) & (bb.z <= ty1) & (bb.w >= ty0);
        }
        unsigned m = __ballot_sync(0xFFFFFFFFu, hit);
        if (lane == 0) sW[warp] = __popc(m);
        __syncthreads();

        int off = total;
        #pragma unroll
        for (int w = 0; w < 8; w++) if (w < warp) off += sW[w];
        int batch = sW[0]+sW[1]+sW[2]+sW[3]+sW[4]+sW[5]+sW[6]+sW[7];

        if (hit) {
            int pos = off + __popc(m & ((1u << lane) - 1u));
            sA[pos] = dgA[gi];
            sB[pos] = dgB[gi];
        }
        total += batch;
        __syncthreads();
    }

    // ---- per-(pixel, segment) compositing over contiguous chunk ----
    int per = (total + NSEG - 1) >> 2;
    int s0  = seg * per;
    int s1  = s0 + per; if (s1 > total) s1 = total;

    float T = 1.f, c = 0.f;
    for (int j = s0; j < s1; j++) {
        float4 A = sA[j];
        float4 B = sB[j];
        float dx = pxc - A.x;
        float dy = pyc - A.y;
        float e = fmaf(A.z*dx, dx, fmaf(B.x*dy, dy, A.w*dx*dy));
        float alpha = B.y * fast_ex2(-e);
        alpha = fminf(alpha, 0.999f);
        if (e >= 0.f && alpha >= (1.0f/255.0f)) {
            c = fmaf(alpha*T, B.z, c);
            T *= (1.f - alpha);
            if (T <= 1e-4f) break;   // tail contribution < 1e-4 absolute
        }
    }
    segC[seg][pix] = c;
    segT[seg][pix] = T;
    __syncthreads();

    // ---- front-to-back combine of the 4 segments ----
    if (seg == 0) {
        float img = c;
        float Tp  = T;
        #pragma unroll
        for (int s = 1; s < NSEG; s++) {
            img = fmaf(Tp, segC[s][pix], img);
            Tp *= segT[s][pix];
        }
        out[y*WIDTH + x] = img;
    }
}

// ---------------------------------------------------------------------------
extern "C" void kernel_launch(void* const* d_in, const int* in_sizes, int n_in,
                              void* d_out, int out_size)
{
    const float* means   = (const float*)d_in[0];
    const float* quats   = (const float*)d_in[1];
    const float* scales  = (const float*)d_in[2];
    const float* opac    = (const float*)d_in[3];
    const float* rgbs    = (const float*)d_in[4];
    const float* viewmat = (const float*)d_in[5];
    const float* Km      = (const float*)d_in[6];
    int n = in_sizes[3];            // opacities: one per gaussian
    if (n > MAXN) n = MAXN;

    prep_kernel<<<1, 1024>>>(means, quats, scales, opac, rgbs, viewmat, Km, n);
    render_kernel<<<1024, 256>>>((float*)d_out, n);
}